// round 7
// baseline (speedup 1.0000x reference)
#include <cuda_runtime.h>
#include <cuda_bf16.h>
#include <math.h>

#define N_NODES 10000
#define N_EDGES 160000
#define H 128
#define E_RBF 20
#define CUTOFF 5.0f
#define PI_F 3.14159265358979f

typedef unsigned long long u64;
typedef unsigned int u32;

// ---------------- scratch ----------------
__device__ float g_ns[N_NODES * H];
__device__ float g_nvA[N_NODES * 3 * H];
__device__ float g_nvB[N_NODES * 3 * H];
__device__ float g_hidden[N_NODES * H];
__device__ float g_big[N_NODES * 3 * H];
__device__ float g_UV[N_NODES * 3 * 256];
__device__ float g_mlpin[N_NODES * 2 * H];
__device__ float g_UVw[3 * 128 * 256];
__device__ float g_UVb[3 * 256];
// CSR sort + sorted-position per-edge precompute
__device__ int    g_count[N_NODES];
__device__ int    g_offset[N_NODES + 1];
__device__ int    g_ssrc[N_EDGES];
__device__ int    g_sdst[N_EDGES];
__device__ float4 g_eunit[N_EDGES];  // {ux, uy, uz, fcut}
__device__ float4 g_epre[N_EDGES];   // {sin(x), 2cos(x), fcut/d, 0}

// ---------------- helpers ----------------
__device__ __forceinline__ u64 pack2(float x, float y) {
    u64 r; asm("mov.b64 %0,{%1,%2};" : "=l"(r) : "f"(x), "f"(y)); return r;
}
__device__ __forceinline__ void unpack2(u64 v, float& x, float& y) {
    asm("mov.b64 {%0,%1},%2;" : "=f"(x), "=f"(y) : "l"(v));
}
__device__ __forceinline__ u64 fma2(u64 a, u64 b, u64 c) {
    u64 d; asm("fma.rn.f32x2 %0,%1,%2,%3;" : "=l"(d) : "l"(a), "l"(b), "l"(c)); return d;
}
__device__ __forceinline__ u64 mul2(u64 a, u64 b) {
    u64 d; asm("mul.rn.f32x2 %0,%1,%2;" : "=l"(d) : "l"(a), "l"(b)); return d;
}
__device__ __forceinline__ void red4(float* p, float x, float y, float z, float w) {
    asm volatile("red.global.add.v4.f32 [%0], {%1,%2,%3,%4};"
                 :: "l"(p), "f"(x), "f"(y), "f"(z), "f"(w) : "memory");
}
__device__ __forceinline__ float silu_f(float x) { return x / (1.0f + expf(-x)); }
__device__ __forceinline__ float tf32rna(float x) {
    u32 r; asm("cvt.rna.tf32.f32 %0, %1;" : "=r"(r) : "f"(x));
    return __uint_as_float(r);
}

#define MMA_TF32(cc, aa, bb)                                                      \
    asm volatile("mma.sync.aligned.m16n8k8.row.col.f32.tf32.tf32.f32 "            \
                 "{%0,%1,%2,%3},{%4,%5,%6,%7},{%8,%9},{%0,%1,%2,%3};"             \
                 : "+f"((cc)[0]), "+f"((cc)[1]), "+f"((cc)[2]), "+f"((cc)[3])     \
                 : "r"((aa)[0]), "r"((aa)[1]), "r"((aa)[2]), "r"((aa)[3]),        \
                   "r"((bb)[0]), "r"((bb)[1]))

#define LDSM4(r0, r1, r2, r3, addr)                                               \
    asm volatile("ldmatrix.sync.aligned.m8n8.x4.shared.b16 {%0,%1,%2,%3},[%4];"   \
                 : "=r"(r0), "=r"(r1), "=r"(r2), "=r"(r3) : "r"(addr))

// ---------------- init ----------------
__global__ void init_kernel(const int* __restrict__ z, const float* __restrict__ embed) {
    int i = blockIdx.x * blockDim.x + threadIdx.x;
    if (i >= N_NODES * 3 * H) return;
    g_nvA[i] = 0.0f;
    g_nvB[i] = 0.0f;
    if (i < N_NODES * H) {
        int n = i >> 7, h = i & 127;
        g_ns[i] = embed[z[n] * H + h];
    }
    if (i < N_NODES) g_count[i] = 0;
}

// ---------------- dst histogram ----------------
__global__ void hist_kernel(const int* __restrict__ edge) {
    int e = blockIdx.x * blockDim.x + threadIdx.x;
    if (e >= N_EDGES) return;
    atomicAdd(&g_count[edge[2 * e]], 1);
}

// ---------------- exclusive scan of counts ----------------
__global__ __launch_bounds__(1024)
void scan_kernel() {
    __shared__ int part[1024];
    const int t = threadIdx.x;
    const int CH = (N_NODES + 1023) / 1024;
    const int base = t * CH;
    int s = 0;
    for (int i = 0; i < CH; i++) {
        int idx = base + i;
        if (idx < N_NODES) s += g_count[idx];
    }
    part[t] = s;
    __syncthreads();
    for (int off = 1; off < 1024; off <<= 1) {
        int v = (t >= off) ? part[t - off] : 0;
        __syncthreads();
        part[t] += v;
        __syncthreads();
    }
    int run = (t > 0) ? part[t - 1] : 0;
    for (int i = 0; i < CH; i++) {
        int idx = base + i;
        if (idx < N_NODES) {
            g_offset[idx] = run;
            run += g_count[idx];
            g_count[idx] = 0;
        }
    }
    if (t == 1023) g_offset[N_NODES] = part[1023];
}

// ---------------- build sorted arrays + per-edge invariants ----------------
__global__ void build_kernel(const int* __restrict__ edge,
                             const float* __restrict__ ediff,
                             const float* __restrict__ edist) {
    int e = blockIdx.x * blockDim.x + threadIdx.x;
    if (e >= N_EDGES) return;
    int dst = edge[2 * e], src = edge[2 * e + 1];
    int pos = g_offset[dst] + atomicAdd(&g_count[dst], 1);
    float d = edist[e];
    float sn, cs;
    sincosf(d * (PI_F / CUTOFF), &sn, &cs);
    float fcv = (d < CUTOFF) ? 0.5f * (cs + 1.0f) : 0.0f;
    float inv = 1.0f / d;
    g_ssrc[pos]  = src;
    g_sdst[pos]  = dst;
    g_eunit[pos] = make_float4(ediff[3 * e] * inv, ediff[3 * e + 1] * inv,
                               ediff[3 * e + 2] * inv, fcv);
    g_epre[pos]  = make_float4(sn, 2.0f * cs, inv * fcv, 0.0f);
}

// ---------------- pack [U_w | V_w] ----------------
__global__ void pack_uv_kernel(const float* __restrict__ Uw, const float* __restrict__ Ub,
                               const float* __restrict__ Vw, const float* __restrict__ Vb) {
    int i = blockIdx.x * blockDim.x + threadIdx.x;
    if (i < 3 * 128 * 256) {
        int l = i / (128 * 256), r = (i / 256) & 127, c = i & 255;
        g_UVw[i] = (c < 128) ? Uw[(size_t)l * 16384 + r * 128 + c]
                             : Vw[(size_t)l * 16384 + r * 128 + (c - 128)];
    }
    if (i < 3 * 256) {
        int l = i / 256, c = i & 255;
        g_UVb[i] = (c < 128) ? Ub[l * 128 + c] : Vb[l * 128 + (c - 128)];
    }
}

// ---------------- TF32 tensor-core GEMM with ldmatrix fragments ----------------
// As: [m][k] (pad 20). Bs: [n][k] (pad 20, transposed at store).
template<bool SILU>
__global__ __launch_bounds__(256)
void mma_gemm(const float* __restrict__ A, const float* __restrict__ B,
              const float* __restrict__ bias, float* __restrict__ C,
              int M, int N, int K) {
    __shared__ float As[2][128][20];
    __shared__ float Bs[2][128][20];
    const int t    = threadIdx.x;
    const int w    = t >> 5, lane = t & 31;
    const int g    = lane >> 2, tg = lane & 3;
    const int wm   = (w & 1) * 64;
    const int wn   = (w >> 1) * 32;
    const int m0   = blockIdx.y * 128;
    const int n0   = blockIdx.x * 128;

    // ldmatrix lane geometry: row within 16-tile, k-offset 0/4
    const int lrow = (lane & 7) + ((lane >> 3) & 1) * 8;
    const int lk   = ((lane >> 4) & 1) * 4;

    const u32 asb0 = (u32)__cvta_generic_to_shared(&As[0][0][0]);
    const u32 asb1 = (u32)__cvta_generic_to_shared(&As[1][0][0]);
    const u32 bsb0 = (u32)__cvta_generic_to_shared(&Bs[0][0][0]);
    const u32 bsb1 = (u32)__cvta_generic_to_shared(&Bs[1][0][0]);

    float c[4][4][4];
#pragma unroll
    for (int i = 0; i < 4; i++)
#pragma unroll
        for (int j = 0; j < 4; j++)
#pragma unroll
            for (int q = 0; q < 4; q++) c[i][j][q] = 0.0f;

    // A tile loads: 2 float4 per thread (128 rows x 16 k)
    const int as  = t * 2;
    const int ar0 = as >> 2,        ak0 = (as & 3) << 2;
    const int ar1 = (as + 1) >> 2,  ak1 = ((as + 1) & 3) << 2;
    // B tile loads: s = 2t+i: k = s & 15, q = s >> 4 (n4 = 4q)
    const int bk0 = (2 * t) & 15,      bq0 = (2 * t) >> 4;
    const int bk1 = (2 * t + 1) & 15,  bq1 = (2 * t + 1) >> 4;

    float4 va0, va1, vb0, vb1;
    const float4 z4 = make_float4(0.f, 0.f, 0.f, 0.f);

    va0 = (m0 + ar0 < M) ? *(const float4*)(A + (size_t)(m0 + ar0) * K + ak0) : z4;
    va1 = (m0 + ar1 < M) ? *(const float4*)(A + (size_t)(m0 + ar1) * K + ak1) : z4;
    vb0 = *(const float4*)(B + (size_t)bk0 * N + n0 + 4 * bq0);
    vb1 = *(const float4*)(B + (size_t)bk1 * N + n0 + 4 * bq1);
    {
        float* p0 = &As[0][ar0][ak0];
        p0[0] = tf32rna(va0.x); p0[1] = tf32rna(va0.y); p0[2] = tf32rna(va0.z); p0[3] = tf32rna(va0.w);
        float* p1 = &As[0][ar1][ak1];
        p1[0] = tf32rna(va1.x); p1[1] = tf32rna(va1.y); p1[2] = tf32rna(va1.z); p1[3] = tf32rna(va1.w);
        Bs[0][4 * bq0 + 0][bk0] = tf32rna(vb0.x);
        Bs[0][4 * bq0 + 1][bk0] = tf32rna(vb0.y);
        Bs[0][4 * bq0 + 2][bk0] = tf32rna(vb0.z);
        Bs[0][4 * bq0 + 3][bk0] = tf32rna(vb0.w);
        Bs[0][4 * bq1 + 0][bk1] = tf32rna(vb1.x);
        Bs[0][4 * bq1 + 1][bk1] = tf32rna(vb1.y);
        Bs[0][4 * bq1 + 2][bk1] = tf32rna(vb1.z);
        Bs[0][4 * bq1 + 3][bk1] = tf32rna(vb1.w);
    }
    __syncthreads();

    const int nk = K >> 4;
    for (int kt = 0; kt < nk; kt++) {
        const int s = kt & 1;
        const u32 asb = s ? asb1 : asb0;
        const u32 bsb = s ? bsb1 : bsb0;
        if (kt + 1 < nk) {
            const int k0 = (kt + 1) << 4;
            va0 = (m0 + ar0 < M) ? *(const float4*)(A + (size_t)(m0 + ar0) * K + k0 + ak0) : z4;
            va1 = (m0 + ar1 < M) ? *(const float4*)(A + (size_t)(m0 + ar1) * K + k0 + ak1) : z4;
            vb0 = *(const float4*)(B + (size_t)(k0 + bk0) * N + n0 + 4 * bq0);
            vb1 = *(const float4*)(B + (size_t)(k0 + bk1) * N + n0 + 4 * bq1);
        }
#pragma unroll
        for (int kk = 0; kk < 2; kk++) {
            const int kb = kk * 8;
            u32 a[4][4];
#pragma unroll
            for (int mt = 0; mt < 4; mt++) {
                u32 addr = asb + (u32)(((wm + mt * 16 + lrow) * 20 + kb + lk) * 4);
                LDSM4(a[mt][0], a[mt][1], a[mt][2], a[mt][3], addr);
            }
            u32 bA[4], bB[4];
            {
                u32 addr0 = bsb + (u32)(((wn + lrow) * 20 + kb + lk) * 4);
                u32 addr1 = bsb + (u32)(((wn + 16 + lrow) * 20 + kb + lk) * 4);
                LDSM4(bA[0], bA[1], bA[2], bA[3], addr0);
                LDSM4(bB[0], bB[1], bB[2], bB[3], addr1);
            }
            u32 b[4][2];
            b[0][0] = bA[0]; b[0][1] = bA[2];
            b[1][0] = bA[1]; b[1][1] = bA[3];
            b[2][0] = bB[0]; b[2][1] = bB[2];
            b[3][0] = bB[1]; b[3][1] = bB[3];
#pragma unroll
            for (int mt = 0; mt < 4; mt++)
#pragma unroll
                for (int nt = 0; nt < 4; nt++)
                    MMA_TF32(c[mt][nt], a[mt], b[nt]);
        }
        if (kt + 1 < nk) {
            const int ss = s ^ 1;
            float* p0 = &As[ss][ar0][ak0];
            p0[0] = tf32rna(va0.x); p0[1] = tf32rna(va0.y); p0[2] = tf32rna(va0.z); p0[3] = tf32rna(va0.w);
            float* p1 = &As[ss][ar1][ak1];
            p1[0] = tf32rna(va1.x); p1[1] = tf32rna(va1.y); p1[2] = tf32rna(va1.z); p1[3] = tf32rna(va1.w);
            Bs[ss][4 * bq0 + 0][bk0] = tf32rna(vb0.x);
            Bs[ss][4 * bq0 + 1][bk0] = tf32rna(vb0.y);
            Bs[ss][4 * bq0 + 2][bk0] = tf32rna(vb0.z);
            Bs[ss][4 * bq0 + 3][bk0] = tf32rna(vb0.w);
            Bs[ss][4 * bq1 + 0][bk1] = tf32rna(vb1.x);
            Bs[ss][4 * bq1 + 1][bk1] = tf32rna(vb1.y);
            Bs[ss][4 * bq1 + 2][bk1] = tf32rna(vb1.z);
            Bs[ss][4 * bq1 + 3][bk1] = tf32rna(vb1.w);
            __syncthreads();
        }
    }

#pragma unroll
    for (int nt = 0; nt < 4; nt++) {
        const int col = n0 + wn + nt * 8 + 2 * tg;
        const float2 bb = *(const float2*)&bias[col];
#pragma unroll
        for (int mt = 0; mt < 4; mt++) {
            const int r0 = m0 + wm + mt * 16 + g;
            float v0 = c[mt][nt][0] + bb.x, v1 = c[mt][nt][1] + bb.y;
            float v2 = c[mt][nt][2] + bb.x, v3 = c[mt][nt][3] + bb.y;
            if (SILU) { v0 = silu_f(v0); v1 = silu_f(v1); v2 = silu_f(v2); v3 = silu_f(v3); }
            if (r0 < M)     *(float2*)(C + (size_t)r0 * N + col)       = make_float2(v0, v1);
            if (r0 + 8 < M) *(float2*)(C + (size_t)(r0 + 8) * N + col) = make_float2(v2, v3);
        }
    }
}

// ---------------- edge kernel: 16 sorted edges/warp, dst-segmented reduction ----------------
__global__ __launch_bounds__(256, 2)
void edge_seg_kernel(const float* __restrict__ Wf,
                     const float* __restrict__ bf,
                     const float* __restrict__ so,
                     const float* __restrict__ nv_r,
                     float* __restrict__ ns_acc,
                     float* __restrict__ nv_acc)
{
    __shared__ float sW[E_RBF * 384 + 384];
    for (int i = threadIdx.x; i < E_RBF * 384; i += blockDim.x) sW[i] = Wf[i];
    for (int i = threadIdx.x; i < 384; i += blockDim.x) sW[E_RBF * 384 + i] = bf[i];
    __syncthreads();
    const u64* sW2 = (const u64*)sW;
    const u64* sB2 = (const u64*)(sW + E_RBF * 384);

    const int lane = threadIdx.x & 31;
    const int l2   = lane * 2;
    const int warp = (blockIdx.x * blockDim.x + threadIdx.x) >> 5;
    const int jb   = warp * 16;
    if (jb >= N_EDGES) return;

    const u64 Z = pack2(0.0f, 0.0f);
    u64 ans0 = Z, ans1 = Z;
    u64 anv0 = Z, anv1 = Z, anv2 = Z, anv3 = Z, anv4 = Z, anv5 = Z;
    int cur = g_sdst[jb];

#define FLUSH(D)                                                                  \
    do {                                                                          \
        float f0, f1, f2, f3;                                                     \
        unpack2(ans0, f0, f1); unpack2(ans1, f2, f3);                             \
        red4(ns_acc + (size_t)(D) * H + 4 * lane, f0, f1, f2, f3);                \
        float* bp_ = nv_acc + (size_t)(D) * 384 + 4 * lane;                       \
        unpack2(anv0, f0, f1); unpack2(anv1, f2, f3); red4(bp_,       f0, f1, f2, f3); \
        unpack2(anv2, f0, f1); unpack2(anv3, f2, f3); red4(bp_ + 128, f0, f1, f2, f3); \
        unpack2(anv4, f0, f1); unpack2(anv5, f2, f3); red4(bp_ + 256, f0, f1, f2, f3); \
        ans0 = ans1 = anv0 = anv1 = anv2 = anv3 = anv4 = anv5 = Z;                \
    } while (0)

    for (int j = jb; j < jb + 16; j += 4) {
        int src[4], dst[4];
        float invf[4], sC[4], sP[4], c2[4], ux[4], uy[4], uz[4];
        u64 a0a[4], a0b[4], a1a[4], a1b[4], a2a[4], a2b[4];
#pragma unroll
        for (int u = 0; u < 4; u++) {
            int p = j + u;
            src[u] = g_ssrc[p];
            dst[u] = g_sdst[p];
            float4 un = g_eunit[p];
            float4 pr = g_epre[p];
            ux[u] = un.x; uy[u] = un.y; uz[u] = un.z;
            float fcv = un.w;
            invf[u] = pr.z; sC[u] = pr.x; sP[u] = 0.0f; c2[u] = pr.y;
            u64 fcp = pack2(fcv, fcv);
            a0a[u] = mul2(sB2[l2],       fcp); a0b[u] = mul2(sB2[l2 + 1],       fcp);
            a1a[u] = mul2(sB2[64 + l2],  fcp); a1b[u] = mul2(sB2[64 + l2 + 1],  fcp);
            a2a[u] = mul2(sB2[128 + l2], fcp); a2b[u] = mul2(sB2[128 + l2 + 1], fcp);
        }
#pragma unroll 4
        for (int n = 0; n < E_RBF; n++) {
            const u64* wn = sW2 + n * 192 + l2;
            u64 w0a = wn[0],   w0b = wn[1];
            u64 w1a = wn[64],  w1b = wn[65];
            u64 w2a = wn[128], w2b = wn[129];
#pragma unroll
            for (int u = 0; u < 4; u++) {
                float r = sC[u] * invf[u];
                u64 rp = pack2(r, r);
                a0a[u] = fma2(rp, w0a, a0a[u]); a0b[u] = fma2(rp, w0b, a0b[u]);
                a1a[u] = fma2(rp, w1a, a1a[u]); a1b[u] = fma2(rp, w1b, a1b[u]);
                a2a[u] = fma2(rp, w2a, a2a[u]); a2b[u] = fma2(rp, w2b, a2b[u]);
                float tn = fmaf(c2[u], sC[u], -sP[u]);
                sP[u] = sC[u]; sC[u] = tn;
            }
        }
#pragma unroll
        for (int u = 0; u < 4; u++) {
            if (dst[u] != cur) {
                FLUSH(cur);
                cur = dst[u];
            }
            const u64* so2 = (const u64*)(so + (size_t)src[u] * 384);
            u64 g0a = mul2(a0a[u], so2[l2]);       u64 g0b = mul2(a0b[u], so2[l2 + 1]);
            u64 g1a = mul2(a1a[u], so2[64 + l2]);  u64 g1b = mul2(a1b[u], so2[64 + l2 + 1]);
            ans0 = fma2(a2a[u], so2[128 + l2],     ans0);
            ans1 = fma2(a2b[u], so2[128 + l2 + 1], ans1);

            const u64* nv2 = (const u64*)(nv_r + (size_t)src[u] * 384);
            {
                u64 up = pack2(ux[u], ux[u]);
                anv0 = fma2(nv2[l2],     g0a, fma2(up, g1a, anv0));
                anv1 = fma2(nv2[l2 + 1], g0b, fma2(up, g1b, anv1));
            }
            {
                u64 up = pack2(uy[u], uy[u]);
                anv2 = fma2(nv2[64 + l2],     g0a, fma2(up, g1a, anv2));
                anv3 = fma2(nv2[64 + l2 + 1], g0b, fma2(up, g1b, anv3));
            }
            {
                u64 up = pack2(uz[u], uz[u]);
                anv4 = fma2(nv2[128 + l2],     g0a, fma2(up, g1a, anv4));
                anv5 = fma2(nv2[128 + l2 + 1], g0b, fma2(up, g1b, anv5));
            }
        }
    }
    FLUSH(cur);
#undef FLUSH
}

// ---------------- Vv norm + concat into mlp_in ----------------
__global__ void norm_kernel() {
    int i = blockIdx.x * blockDim.x + threadIdx.x;
    if (i >= N_NODES * H) return;
    int n = i >> 7, h = i & 127;
    size_t base = (size_t)(3 * n) * 256 + 128 + h;
    float v0 = g_UV[base], v1 = g_UV[base + 256], v2 = g_UV[base + 512];
    g_mlpin[(size_t)n * 256 + h]       = sqrtf(v0 * v0 + v1 * v1 + v2 * v2);
    g_mlpin[(size_t)n * 256 + 128 + h] = g_ns[i];
}

// ---------------- gated update ----------------
__global__ void update_kernel() {
    int i = blockIdx.x * blockDim.x + threadIdx.x;
    if (i >= N_NODES * H) return;
    int n = i >> 7, h = i & 127;
    const float* mo = g_big + (size_t)n * 384;
    float a_vv = mo[h], a_sv = mo[128 + h], a_ss = mo[256 + h];
    size_t nvb = (size_t)n * 384 + h;
    size_t uvb = (size_t)(3 * n) * 256 + h;
    float dot = 0.0f;
#pragma unroll
    for (int d = 0; d < 3; d++) {
        float u = g_UV[uvb + d * 256];
        float v = g_UV[uvb + d * 256 + 128];
        dot = fmaf(u, v, dot);
        float nvnew = g_nvB[nvb + d * 128] + a_vv * u;
        g_nvA[nvb + d * 128] = nvnew;
        g_nvB[nvb + d * 128] = nvnew;
    }
    g_ns[i] += a_sv * dot + a_ss;
}

// ---------------- host launch ----------------
static void gemm(const float* A, const float* B, const float* bias, float* C,
                 int M, int N, int K, bool silu) {
    dim3 g(N / 128, (M + 127) / 128);
    if (silu) mma_gemm<true><<<g, 256>>>(A, B, bias, C, M, N, K);
    else      mma_gemm<false><<<g, 256>>>(A, B, bias, C, M, N, K);
}

extern "C" void kernel_launch(void* const* d_in, const int* in_sizes, int n_in,
                              void* d_out, int out_size) {
    const int*   z            = (const int*)d_in[0];
    const int*   edge         = (const int*)d_in[1];
    const float* edge_diff    = (const float*)d_in[2];
    const float* edge_dist    = (const float*)d_in[3];
    const float* embed        = (const float*)d_in[4];
    const float* msg_filter_w = (const float*)d_in[5];
    const float* msg_filter_b = (const float*)d_in[6];
    const float* msg_w1       = (const float*)d_in[7];
    const float* msg_b1       = (const float*)d_in[8];
    const float* msg_w2       = (const float*)d_in[9];
    const float* msg_b2       = (const float*)d_in[10];
    const float* upd_U_w      = (const float*)d_in[11];
    const float* upd_U_b      = (const float*)d_in[12];
    const float* upd_V_w      = (const float*)d_in[13];
    const float* upd_V_b      = (const float*)d_in[14];
    const float* upd_w1       = (const float*)d_in[15];
    const float* upd_b1       = (const float*)d_in[16];
    const float* upd_w2       = (const float*)d_in[17];
    const float* upd_b2       = (const float*)d_in[18];
    const float* ro_w1        = (const float*)d_in[19];
    const float* ro_b1        = (const float*)d_in[20];
    const float* ro_w2        = (const float*)d_in[21];
    const float* ro_b2        = (const float*)d_in[22];
    float* out = (float*)d_out;

    float *ns, *nvA, *nvB, *hidden, *big, *UV, *mlpin, *UVw, *UVb;
    cudaGetSymbolAddress((void**)&ns,     g_ns);
    cudaGetSymbolAddress((void**)&nvA,    g_nvA);
    cudaGetSymbolAddress((void**)&nvB,    g_nvB);
    cudaGetSymbolAddress((void**)&hidden, g_hidden);
    cudaGetSymbolAddress((void**)&big,    g_big);
    cudaGetSymbolAddress((void**)&UV,     g_UV);
    cudaGetSymbolAddress((void**)&mlpin,  g_mlpin);
    cudaGetSymbolAddress((void**)&UVw,    g_UVw);
    cudaGetSymbolAddress((void**)&UVb,    g_UVb);

    init_kernel<<<(N_NODES * 3 * H + 255) / 256, 256>>>(z, embed);
    hist_kernel<<<(N_EDGES + 255) / 256, 256>>>(edge);
    scan_kernel<<<1, 1024>>>();
    build_kernel<<<(N_EDGES + 255) / 256, 256>>>(edge, edge_diff, edge_dist);
    pack_uv_kernel<<<(3 * 128 * 256 + 255) / 256, 256>>>(upd_U_w, upd_U_b, upd_V_w, upd_V_b);

    for (int l = 0; l < 3; l++) {
        gemm(ns, msg_w1 + (size_t)l * 128 * 128, msg_b1 + l * 128, hidden,
             N_NODES, 128, 128, true);
        gemm(hidden, msg_w2 + (size_t)l * 128 * 384, msg_b2 + l * 384, big,
             N_NODES, 384, 128, false);
        edge_seg_kernel<<<(N_EDGES / 16 * 32) / 256, 256>>>(
            msg_filter_w + (size_t)l * 20 * 384, msg_filter_b + l * 384,
            big, nvA, ns, nvB);
        gemm(nvB, UVw + (size_t)l * 128 * 256, UVb + l * 256, UV,
             N_NODES * 3, 256, 128, false);
        norm_kernel<<<(N_NODES * H + 255) / 256, 256>>>();
        gemm(mlpin, upd_w1 + (size_t)l * 256 * 128, upd_b1 + l * 128, hidden,
             N_NODES, 128, 256, true);
        gemm(hidden, upd_w2 + (size_t)l * 128 * 384, upd_b2 + l * 384, big,
             N_NODES, 384, 128, false);
        update_kernel<<<(N_NODES * H + 255) / 256, 256>>>();
    }

    gemm(ns, ro_w1, ro_b1, hidden, N_NODES, 128, 128, true);
    gemm(hidden, ro_w2, ro_b2, out, N_NODES, 128, 128, false);
}

// round 8
// speedup vs baseline: 1.0568x; 1.0568x over previous
#include <cuda_runtime.h>
#include <cuda_bf16.h>
#include <math.h>

#define N_NODES 10000
#define N_EDGES 160000
#define H 128
#define E_RBF 20
#define CUTOFF 5.0f
#define PI_F 3.14159265358979f

typedef unsigned long long u64;
typedef unsigned int u32;

// ---------------- scratch ----------------
__device__ float g_ns[N_NODES * H];
__device__ float g_nvA[N_NODES * 3 * H];
__device__ float g_nvB[N_NODES * 3 * H];
__device__ float g_hidden[N_NODES * H];
__device__ float g_big[N_NODES * 3 * H];
__device__ float g_UV[N_NODES * 3 * 256];
__device__ float g_mlpin[N_NODES * 2 * H];
__device__ float g_UVw[3 * 128 * 256];
__device__ float g_UVb[3 * 256];
// CSR sort + sorted-position per-edge precompute
__device__ int    g_count[N_NODES];
__device__ int    g_offset[N_NODES + 1];
__device__ int    g_ssrc[N_EDGES];
__device__ int    g_sdst[N_EDGES];
__device__ float4 g_eunit[N_EDGES];  // {ux, uy, uz, fcut}
__device__ float4 g_epre[N_EDGES];   // {sin(x), 2cos(x), fcut/d, 0}

// ---------------- helpers ----------------
__device__ __forceinline__ u64 pack2(float x, float y) {
    u64 r; asm("mov.b64 %0,{%1,%2};" : "=l"(r) : "f"(x), "f"(y)); return r;
}
__device__ __forceinline__ void unpack2(u64 v, float& x, float& y) {
    asm("mov.b64 {%0,%1},%2;" : "=f"(x), "=f"(y) : "l"(v));
}
__device__ __forceinline__ u64 fma2(u64 a, u64 b, u64 c) {
    u64 d; asm("fma.rn.f32x2 %0,%1,%2,%3;" : "=l"(d) : "l"(a), "l"(b), "l"(c)); return d;
}
__device__ __forceinline__ u64 mul2(u64 a, u64 b) {
    u64 d; asm("mul.rn.f32x2 %0,%1,%2;" : "=l"(d) : "l"(a), "l"(b)); return d;
}
__device__ __forceinline__ void red4(float* p, float x, float y, float z, float w) {
    asm volatile("red.global.add.v4.f32 [%0], {%1,%2,%3,%4};"
                 :: "l"(p), "f"(x), "f"(y), "f"(z), "f"(w) : "memory");
}
__device__ __forceinline__ float silu_f(float x) { return x / (1.0f + expf(-x)); }
__device__ __forceinline__ float tf32rna(float x) {
    u32 r; asm("cvt.rna.tf32.f32 %0, %1;" : "=r"(r) : "f"(x));
    return __uint_as_float(r);
}

#define MMA_TF32(cc, aa, bb)                                                      \
    asm volatile("mma.sync.aligned.m16n8k8.row.col.f32.tf32.tf32.f32 "            \
                 "{%0,%1,%2,%3},{%4,%5,%6,%7},{%8,%9},{%0,%1,%2,%3};"             \
                 : "+f"((cc)[0]), "+f"((cc)[1]), "+f"((cc)[2]), "+f"((cc)[3])     \
                 : "r"((aa)[0]), "r"((aa)[1]), "r"((aa)[2]), "r"((aa)[3]),        \
                   "r"((bb)[0]), "r"((bb)[1]))

// ---------------- init ----------------
__global__ void init_kernel(const int* __restrict__ z, const float* __restrict__ embed) {
    int i = blockIdx.x * blockDim.x + threadIdx.x;
    if (i >= N_NODES * 3 * H) return;
    g_nvA[i] = 0.0f;
    g_nvB[i] = 0.0f;
    if (i < N_NODES * H) {
        int n = i >> 7, h = i & 127;
        g_ns[i] = embed[z[n] * H + h];
    }
    if (i < N_NODES) g_count[i] = 0;
}

// ---------------- dst histogram ----------------
__global__ void hist_kernel(const int* __restrict__ edge) {
    int e = blockIdx.x * blockDim.x + threadIdx.x;
    if (e >= N_EDGES) return;
    atomicAdd(&g_count[edge[2 * e]], 1);
}

// ---------------- exclusive scan of counts ----------------
__global__ __launch_bounds__(1024)
void scan_kernel() {
    __shared__ int part[1024];
    const int t = threadIdx.x;
    const int CH = (N_NODES + 1023) / 1024;
    const int base = t * CH;
    int s = 0;
    for (int i = 0; i < CH; i++) {
        int idx = base + i;
        if (idx < N_NODES) s += g_count[idx];
    }
    part[t] = s;
    __syncthreads();
    for (int off = 1; off < 1024; off <<= 1) {
        int v = (t >= off) ? part[t - off] : 0;
        __syncthreads();
        part[t] += v;
        __syncthreads();
    }
    int run = (t > 0) ? part[t - 1] : 0;
    for (int i = 0; i < CH; i++) {
        int idx = base + i;
        if (idx < N_NODES) {
            g_offset[idx] = run;
            run += g_count[idx];
            g_count[idx] = 0;
        }
    }
    if (t == 1023) g_offset[N_NODES] = part[1023];
}

// ---------------- build sorted arrays + per-edge invariants ----------------
__global__ void build_kernel(const int* __restrict__ edge,
                             const float* __restrict__ ediff,
                             const float* __restrict__ edist) {
    int e = blockIdx.x * blockDim.x + threadIdx.x;
    if (e >= N_EDGES) return;
    int dst = edge[2 * e], src = edge[2 * e + 1];
    int pos = g_offset[dst] + atomicAdd(&g_count[dst], 1);
    float d = edist[e];
    float sn, cs;
    sincosf(d * (PI_F / CUTOFF), &sn, &cs);
    float fcv = (d < CUTOFF) ? 0.5f * (cs + 1.0f) : 0.0f;
    float inv = 1.0f / d;
    g_ssrc[pos]  = src;
    g_sdst[pos]  = dst;
    g_eunit[pos] = make_float4(ediff[3 * e] * inv, ediff[3 * e + 1] * inv,
                               ediff[3 * e + 2] * inv, fcv);
    g_epre[pos]  = make_float4(sn, 2.0f * cs, inv * fcv, 0.0f);
}

// ---------------- pack [U_w | V_w] ----------------
__global__ void pack_uv_kernel(const float* __restrict__ Uw, const float* __restrict__ Ub,
                               const float* __restrict__ Vw, const float* __restrict__ Vb) {
    int i = blockIdx.x * blockDim.x + threadIdx.x;
    if (i < 3 * 128 * 256) {
        int l = i / (128 * 256), r = (i / 256) & 127, c = i & 255;
        g_UVw[i] = (c < 128) ? Uw[(size_t)l * 16384 + r * 128 + c]
                             : Vw[(size_t)l * 16384 + r * 128 + (c - 128)];
    }
    if (i < 3 * 256) {
        int l = i / 256, c = i & 255;
        g_UVb[i] = (c < 128) ? Ub[l * 128 + c] : Vb[l * 128 + (c - 128)];
    }
}

// ---------------- TF32 tensor-core GEMM (R6 structure, BM templated) ----------------
// BM=128: 8 warps of 64x32 (MT=4). BM=64: 8 warps of 32x32 (MT=2).
template<int BM, bool SILU>
__global__ __launch_bounds__(256, 2)
void mma_gemm(const float* __restrict__ A, const float* __restrict__ B,
              const float* __restrict__ bias, float* __restrict__ C,
              int M, int N, int K) {
    constexpr int MT = BM / 32;          // 4 or 2
    __shared__ float As[2][BM][20];
    __shared__ float Bs[2][16][136];
    const int t    = threadIdx.x;
    const int w    = t >> 5, lane = t & 31;
    const int g    = lane >> 2, tg = lane & 3;
    const int wm   = (w & 1) * (BM / 2);
    const int wn   = (w >> 1) * 32;
    const int m0   = blockIdx.y * BM;
    const int n0   = blockIdx.x * 128;

    float c[MT][4][4];
#pragma unroll
    for (int i = 0; i < MT; i++)
#pragma unroll
        for (int j = 0; j < 4; j++)
#pragma unroll
            for (int q = 0; q < 4; q++) c[i][j][q] = 0.0f;

    // A tile loads: BM*16 floats; BM=128 -> 2 float4/thread, BM=64 -> 1
    constexpr int ALD = (BM == 128) ? 2 : 1;
    int ar[2], ak[2];
#pragma unroll
    for (int i = 0; i < ALD; i++) {
        int s = t * ALD + i;
        ar[i] = s >> 2;
        ak[i] = (s & 3) << 2;
    }
    const int bs  = t * 2;
    const int bk0 = bs >> 5,        bn0 = (bs & 31) << 2;
    const int bk1 = (bs + 1) >> 5,  bn1 = ((bs + 1) & 31) << 2;

    float4 va[2], vb0, vb1;
    const float4 z4 = make_float4(0.f, 0.f, 0.f, 0.f);

#pragma unroll
    for (int i = 0; i < ALD; i++)
        va[i] = (m0 + ar[i] < M) ? *(const float4*)(A + (size_t)(m0 + ar[i]) * K + ak[i]) : z4;
    vb0 = *(const float4*)(B + (size_t)bk0 * N + n0 + bn0);
    vb1 = *(const float4*)(B + (size_t)bk1 * N + n0 + bn1);
    {
#pragma unroll
        for (int i = 0; i < ALD; i++) {
            float* p = &As[0][ar[i]][ak[i]];
            p[0] = tf32rna(va[i].x); p[1] = tf32rna(va[i].y);
            p[2] = tf32rna(va[i].z); p[3] = tf32rna(va[i].w);
        }
        float* q0 = &Bs[0][bk0][bn0];
        q0[0] = tf32rna(vb0.x); q0[1] = tf32rna(vb0.y); q0[2] = tf32rna(vb0.z); q0[3] = tf32rna(vb0.w);
        float* q1 = &Bs[0][bk1][bn1];
        q1[0] = tf32rna(vb1.x); q1[1] = tf32rna(vb1.y); q1[2] = tf32rna(vb1.z); q1[3] = tf32rna(vb1.w);
    }
    __syncthreads();

    const int nk = K >> 4;
    for (int kt = 0; kt < nk; kt++) {
        const int s = kt & 1;
        if (kt + 1 < nk) {
            const int k0 = (kt + 1) << 4;
#pragma unroll
            for (int i = 0; i < ALD; i++)
                va[i] = (m0 + ar[i] < M) ? *(const float4*)(A + (size_t)(m0 + ar[i]) * K + k0 + ak[i]) : z4;
            vb0 = *(const float4*)(B + (size_t)(k0 + bk0) * N + n0 + bn0);
            vb1 = *(const float4*)(B + (size_t)(k0 + bk1) * N + n0 + bn1);
        }
#pragma unroll
        for (int kk = 0; kk < 2; kk++) {
            const int kb = kk * 8;
            u32 a[MT][4], b[4][2];
#pragma unroll
            for (int mt = 0; mt < MT; mt++) {
                const int r = wm + mt * 16 + g;
                a[mt][0] = __float_as_uint(As[s][r][kb + tg]);
                a[mt][1] = __float_as_uint(As[s][r + 8][kb + tg]);
                a[mt][2] = __float_as_uint(As[s][r][kb + tg + 4]);
                a[mt][3] = __float_as_uint(As[s][r + 8][kb + tg + 4]);
            }
#pragma unroll
            for (int nt = 0; nt < 4; nt++) {
                const int col = wn + nt * 8 + g;
                b[nt][0] = __float_as_uint(Bs[s][kb + tg][col]);
                b[nt][1] = __float_as_uint(Bs[s][kb + tg + 4][col]);
            }
#pragma unroll
            for (int mt = 0; mt < MT; mt++)
#pragma unroll
                for (int nt = 0; nt < 4; nt++)
                    MMA_TF32(c[mt][nt], a[mt], b[nt]);
        }
        if (kt + 1 < nk) {
            const int ss = s ^ 1;
#pragma unroll
            for (int i = 0; i < ALD; i++) {
                float* p = &As[ss][ar[i]][ak[i]];
                p[0] = tf32rna(va[i].x); p[1] = tf32rna(va[i].y);
                p[2] = tf32rna(va[i].z); p[3] = tf32rna(va[i].w);
            }
            float* q0 = &Bs[ss][bk0][bn0];
            q0[0] = tf32rna(vb0.x); q0[1] = tf32rna(vb0.y); q0[2] = tf32rna(vb0.z); q0[3] = tf32rna(vb0.w);
            float* q1 = &Bs[ss][bk1][bn1];
            q1[0] = tf32rna(vb1.x); q1[1] = tf32rna(vb1.y); q1[2] = tf32rna(vb1.z); q1[3] = tf32rna(vb1.w);
            __syncthreads();
        }
    }

#pragma unroll
    for (int nt = 0; nt < 4; nt++) {
        const int col = n0 + wn + nt * 8 + 2 * tg;
        const float2 bb = *(const float2*)&bias[col];
#pragma unroll
        for (int mt = 0; mt < MT; mt++) {
            const int r0 = m0 + wm + mt * 16 + g;
            float v0 = c[mt][nt][0] + bb.x, v1 = c[mt][nt][1] + bb.y;
            float v2 = c[mt][nt][2] + bb.x, v3 = c[mt][nt][3] + bb.y;
            if (SILU) { v0 = silu_f(v0); v1 = silu_f(v1); v2 = silu_f(v2); v3 = silu_f(v3); }
            if (r0 < M)     *(float2*)(C + (size_t)r0 * N + col)       = make_float2(v0, v1);
            if (r0 + 8 < M) *(float2*)(C + (size_t)(r0 + 8) * N + col) = make_float2(v2, v3);
        }
    }
}

// ---------------- edge kernel: 16 sorted edges/warp, dst-segmented reduction ----------------
__global__ __launch_bounds__(256, 2)
void edge_seg_kernel(const float* __restrict__ Wf,
                     const float* __restrict__ bf,
                     const float* __restrict__ so,
                     const float* __restrict__ nv_r,
                     float* __restrict__ ns_acc,
                     float* __restrict__ nv_acc)
{
    __shared__ float sW[E_RBF * 384 + 384];
    for (int i = threadIdx.x; i < E_RBF * 384; i += blockDim.x) sW[i] = Wf[i];
    for (int i = threadIdx.x; i < 384; i += blockDim.x) sW[E_RBF * 384 + i] = bf[i];
    __syncthreads();
    const u64* sW2 = (const u64*)sW;
    const u64* sB2 = (const u64*)(sW + E_RBF * 384);

    const int lane = threadIdx.x & 31;
    const int l2   = lane * 2;
    const int warp = (blockIdx.x * blockDim.x + threadIdx.x) >> 5;
    const int jb   = warp * 16;
    if (jb >= N_EDGES) return;

    const u64 Z = pack2(0.0f, 0.0f);
    u64 ans0 = Z, ans1 = Z;
    u64 anv0 = Z, anv1 = Z, anv2 = Z, anv3 = Z, anv4 = Z, anv5 = Z;
    int cur = g_sdst[jb];

#define FLUSH(D)                                                                  \
    do {                                                                          \
        float f0, f1, f2, f3;                                                     \
        unpack2(ans0, f0, f1); unpack2(ans1, f2, f3);                             \
        red4(ns_acc + (size_t)(D) * H + 4 * lane, f0, f1, f2, f3);                \
        float* bp_ = nv_acc + (size_t)(D) * 384 + 4 * lane;                       \
        unpack2(anv0, f0, f1); unpack2(anv1, f2, f3); red4(bp_,       f0, f1, f2, f3); \
        unpack2(anv2, f0, f1); unpack2(anv3, f2, f3); red4(bp_ + 128, f0, f1, f2, f3); \
        unpack2(anv4, f0, f1); unpack2(anv5, f2, f3); red4(bp_ + 256, f0, f1, f2, f3); \
        ans0 = ans1 = anv0 = anv1 = anv2 = anv3 = anv4 = anv5 = Z;                \
    } while (0)

    for (int j = jb; j < jb + 16; j += 4) {
        int src[4], dst[4];
        float invf[4], sC[4], sP[4], c2[4], ux[4], uy[4], uz[4];
        u64 a0a[4], a0b[4], a1a[4], a1b[4], a2a[4], a2b[4];
#pragma unroll
        for (int u = 0; u < 4; u++) {
            int p = j + u;
            src[u] = g_ssrc[p];
            dst[u] = g_sdst[p];
            float4 un = g_eunit[p];
            float4 pr = g_epre[p];
            ux[u] = un.x; uy[u] = un.y; uz[u] = un.z;
            float fcv = un.w;
            invf[u] = pr.z; sC[u] = pr.x; sP[u] = 0.0f; c2[u] = pr.y;
            u64 fcp = pack2(fcv, fcv);
            a0a[u] = mul2(sB2[l2],       fcp); a0b[u] = mul2(sB2[l2 + 1],       fcp);
            a1a[u] = mul2(sB2[64 + l2],  fcp); a1b[u] = mul2(sB2[64 + l2 + 1],  fcp);
            a2a[u] = mul2(sB2[128 + l2], fcp); a2b[u] = mul2(sB2[128 + l2 + 1], fcp);
        }
#pragma unroll 4
        for (int n = 0; n < E_RBF; n++) {
            const u64* wn = sW2 + n * 192 + l2;
            u64 w0a = wn[0],   w0b = wn[1];
            u64 w1a = wn[64],  w1b = wn[65];
            u64 w2a = wn[128], w2b = wn[129];
#pragma unroll
            for (int u = 0; u < 4; u++) {
                float r = sC[u] * invf[u];
                u64 rp = pack2(r, r);
                a0a[u] = fma2(rp, w0a, a0a[u]); a0b[u] = fma2(rp, w0b, a0b[u]);
                a1a[u] = fma2(rp, w1a, a1a[u]); a1b[u] = fma2(rp, w1b, a1b[u]);
                a2a[u] = fma2(rp, w2a, a2a[u]); a2b[u] = fma2(rp, w2b, a2b[u]);
                float tn = fmaf(c2[u], sC[u], -sP[u]);
                sP[u] = sC[u]; sC[u] = tn;
            }
        }
#pragma unroll
        for (int u = 0; u < 4; u++) {
            if (dst[u] != cur) {
                FLUSH(cur);
                cur = dst[u];
            }
            const u64* so2 = (const u64*)(so + (size_t)src[u] * 384);
            u64 g0a = mul2(a0a[u], so2[l2]);       u64 g0b = mul2(a0b[u], so2[l2 + 1]);
            u64 g1a = mul2(a1a[u], so2[64 + l2]);  u64 g1b = mul2(a1b[u], so2[64 + l2 + 1]);
            ans0 = fma2(a2a[u], so2[128 + l2],     ans0);
            ans1 = fma2(a2b[u], so2[128 + l2 + 1], ans1);

            const u64* nv2 = (const u64*)(nv_r + (size_t)src[u] * 384);
            {
                u64 up = pack2(ux[u], ux[u]);
                anv0 = fma2(nv2[l2],     g0a, fma2(up, g1a, anv0));
                anv1 = fma2(nv2[l2 + 1], g0b, fma2(up, g1b, anv1));
            }
            {
                u64 up = pack2(uy[u], uy[u]);
                anv2 = fma2(nv2[64 + l2],     g0a, fma2(up, g1a, anv2));
                anv3 = fma2(nv2[64 + l2 + 1], g0b, fma2(up, g1b, anv3));
            }
            {
                u64 up = pack2(uz[u], uz[u]);
                anv4 = fma2(nv2[128 + l2],     g0a, fma2(up, g1a, anv4));
                anv5 = fma2(nv2[128 + l2 + 1], g0b, fma2(up, g1b, anv5));
            }
        }
    }
    FLUSH(cur);
#undef FLUSH
}

// ---------------- Vv norm + concat into mlp_in ----------------
__global__ void norm_kernel() {
    int i = blockIdx.x * blockDim.x + threadIdx.x;
    if (i >= N_NODES * H) return;
    int n = i >> 7, h = i & 127;
    size_t base = (size_t)(3 * n) * 256 + 128 + h;
    float v0 = g_UV[base], v1 = g_UV[base + 256], v2 = g_UV[base + 512];
    g_mlpin[(size_t)n * 256 + h]       = sqrtf(v0 * v0 + v1 * v1 + v2 * v2);
    g_mlpin[(size_t)n * 256 + 128 + h] = g_ns[i];
}

// ---------------- gated update ----------------
__global__ void update_kernel() {
    int i = blockIdx.x * blockDim.x + threadIdx.x;
    if (i >= N_NODES * H) return;
    int n = i >> 7, h = i & 127;
    const float* mo = g_big + (size_t)n * 384;
    float a_vv = mo[h], a_sv = mo[128 + h], a_ss = mo[256 + h];
    size_t nvb = (size_t)n * 384 + h;
    size_t uvb = (size_t)(3 * n) * 256 + h;
    float dot = 0.0f;
#pragma unroll
    for (int d = 0; d < 3; d++) {
        float u = g_UV[uvb + d * 256];
        float v = g_UV[uvb + d * 256 + 128];
        dot = fmaf(u, v, dot);
        float nvnew = g_nvB[nvb + d * 128] + a_vv * u;
        g_nvA[nvb + d * 128] = nvnew;
        g_nvB[nvb + d * 128] = nvnew;
    }
    g_ns[i] += a_sv * dot + a_ss;
}

// ---------------- host launch ----------------
static void gemm(const float* A, const float* B, const float* bias, float* C,
                 int M, int N, int K, bool silu) {
    if (N == 128) {
        dim3 g(1, (M + 63) / 64);
        if (silu) mma_gemm<64, true><<<g, 256>>>(A, B, bias, C, M, N, K);
        else      mma_gemm<64, false><<<g, 256>>>(A, B, bias, C, M, N, K);
    } else {
        dim3 g(N / 128, (M + 127) / 128);
        if (silu) mma_gemm<128, true><<<g, 256>>>(A, B, bias, C, M, N, K);
        else      mma_gemm<128, false><<<g, 256>>>(A, B, bias, C, M, N, K);
    }
}

extern "C" void kernel_launch(void* const* d_in, const int* in_sizes, int n_in,
                              void* d_out, int out_size) {
    const int*   z            = (const int*)d_in[0];
    const int*   edge         = (const int*)d_in[1];
    const float* edge_diff    = (const float*)d_in[2];
    const float* edge_dist    = (const float*)d_in[3];
    const float* embed        = (const float*)d_in[4];
    const float* msg_filter_w = (const float*)d_in[5];
    const float* msg_filter_b = (const float*)d_in[6];
    const float* msg_w1       = (const float*)d_in[7];
    const float* msg_b1       = (const float*)d_in[8];
    const float* msg_w2       = (const float*)d_in[9];
    const float* msg_b2       = (const float*)d_in[10];
    const float* upd_U_w      = (const float*)d_in[11];
    const float* upd_U_b      = (const float*)d_in[12];
    const float* upd_V_w      = (const float*)d_in[13];
    const float* upd_V_b      = (const float*)d_in[14];
    const float* upd_w1       = (const float*)d_in[15];
    const float* upd_b1       = (const float*)d_in[16];
    const float* upd_w2       = (const float*)d_in[17];
    const float* upd_b2       = (const float*)d_in[18];
    const float* ro_w1        = (const float*)d_in[19];
    const float* ro_b1        = (const float*)d_in[20];
    const float* ro_w2        = (const float*)d_in[21];
    const float* ro_b2        = (const float*)d_in[22];
    float* out = (float*)d_out;

    float *ns, *nvA, *nvB, *hidden, *big, *UV, *mlpin, *UVw, *UVb;
    cudaGetSymbolAddress((void**)&ns,     g_ns);
    cudaGetSymbolAddress((void**)&nvA,    g_nvA);
    cudaGetSymbolAddress((void**)&nvB,    g_nvB);
    cudaGetSymbolAddress((void**)&hidden, g_hidden);
    cudaGetSymbolAddress((void**)&big,    g_big);
    cudaGetSymbolAddress((void**)&UV,     g_UV);
    cudaGetSymbolAddress((void**)&mlpin,  g_mlpin);
    cudaGetSymbolAddress((void**)&UVw,    g_UVw);
    cudaGetSymbolAddress((void**)&UVb,    g_UVb);

    init_kernel<<<(N_NODES * 3 * H + 255) / 256, 256>>>(z, embed);
    hist_kernel<<<(N_EDGES + 255) / 256, 256>>>(edge);
    scan_kernel<<<1, 1024>>>();
    build_kernel<<<(N_EDGES + 255) / 256, 256>>>(edge, edge_diff, edge_dist);
    pack_uv_kernel<<<(3 * 128 * 256 + 255) / 256, 256>>>(upd_U_w, upd_U_b, upd_V_w, upd_V_b);

    for (int l = 0; l < 3; l++) {
        gemm(ns, msg_w1 + (size_t)l * 128 * 128, msg_b1 + l * 128, hidden,
             N_NODES, 128, 128, true);
        gemm(hidden, msg_w2 + (size_t)l * 128 * 384, msg_b2 + l * 384, big,
             N_NODES, 384, 128, false);
        edge_seg_kernel<<<(N_EDGES / 16 * 32) / 256, 256>>>(
            msg_filter_w + (size_t)l * 20 * 384, msg_filter_b + l * 384,
            big, nvA, ns, nvB);
        gemm(nvB, UVw + (size_t)l * 128 * 256, UVb + l * 256, UV,
             N_NODES * 3, 256, 128, false);
        norm_kernel<<<(N_NODES * H + 255) / 256, 256>>>();
        gemm(mlpin, upd_w1 + (size_t)l * 256 * 128, upd_b1 + l * 128, hidden,
             N_NODES, 128, 256, true);
        gemm(hidden, upd_w2 + (size_t)l * 128 * 384, upd_b2 + l * 384, big,
             N_NODES, 384, 128, false);
        update_kernel<<<(N_NODES * H + 255) / 256, 256>>>();
    }

    gemm(ns, ro_w1, ro_b1, hidden, N_NODES, 128, 128, true);
    gemm(hidden, ro_w2, ro_b2, out, N_NODES, 128, 128, false);
}